// round 2
// baseline (speedup 1.0000x reference)
#include <cuda_runtime.h>
#include <cstdint>

#define DSPAN 1024
#define HID   128
#define FEAT  20
#define NWID  30

// ---------------- device scratch (no allocations allowed) ----------------
__device__ int      g_hist1[65536];
__device__ int      g_hist2[65536];
__device__ int      g_b1, g_need1, g_needeq, g_tiecnt, g_cutoff;
__device__ unsigned g_thr;
__device__ int      g_tie[1024];
__device__ int      g_bcnt[256];
__device__ int      g_boff[256];
__device__ int      g_topi[4096];
__device__ float    g_width[32];

// monotone float->uint transform (order-preserving for all finite floats)
__device__ __forceinline__ unsigned f2u(float f) {
    unsigned b = __float_as_uint(f);
    return b ^ ((unsigned)((int)b >> 31) | 0x80000000u);
}

__device__ __forceinline__ bool sel_pred(unsigned u, int i, unsigned thr, int cut) {
    return (u > thr) || (u == thr && i <= cut);
}

// ---------------- setup: zero histograms + counters ----------------
__global__ void k_setup() {
    int i = blockIdx.x * blockDim.x + threadIdx.x;
    if (i < 65536) g_hist1[i] = 0;
    int j = i - 65536;
    if (j >= 0 && j < 65536) g_hist2[j] = 0;
    if (i == 0) g_tiecnt = 0;
}

// ---------------- width prior scores (30 widths) ----------------
__global__ void k_width(const float* __restrict__ emb,
                        const float* __restrict__ Ww1, const float* __restrict__ bw1,
                        const float* __restrict__ Ww2, const float* __restrict__ bw2) {
    __shared__ float red[128];
    int j = threadIdx.x;  // 0..127
    for (int w = 0; w < NWID; w++) {
        float acc = bw1[j];
        #pragma unroll
        for (int kk = 0; kk < FEAT; kk++)
            acc += emb[w * FEAT + kk] * Ww1[kk * HID + j];
        red[j] = fmaxf(acc, 0.f) * Ww2[j];
        __syncthreads();
        for (int s = 64; s > 0; s >>= 1) {
            if (j < s) red[j] += red[j + s];
            __syncthreads();
        }
        if (j == 0) g_width[w] = red[0] + bw2[0];
        __syncthreads();
    }
}

// ---------------- fused mention-scorer GEMM ----------------
// score[i] = relu(x[i]@W1 + b1) @ W2 + b2 + width_score[widx[i]]
// Block: 64 rows x 128 cols (full H), K tiled by 32. 256 threads, 4x8 micro-tile.
__global__ __launch_bounds__(256, 4)
void k_gemm(const float* __restrict__ x,
            const float* __restrict__ W1, const float* __restrict__ b1,
            const float* __restrict__ W2, const float* __restrict__ b2,
            const int* __restrict__ widx, float* __restrict__ scores, int N) {
    __shared__ float Xs[64 * 36];        // 64 rows x 32 k, padded stride 36
    __shared__ float Ws[32 * 128];       // 32 k x 128 h
    __shared__ float Sred[64 * 17];

    int tid = threadIdx.x;
    int tx = tid & 15;        // col group (8 cols each)
    int ty = tid >> 4;        // row group (4 rows each)
    int m0 = blockIdx.x * 64;

    float acc[4][8];
    #pragma unroll
    for (int r = 0; r < 4; r++)
        #pragma unroll
        for (int j = 0; j < 8; j++) acc[r][j] = 0.f;

    const float* xblk = x + (size_t)m0 * DSPAN;

    for (int kt = 0; kt < DSPAN; kt += 32) {
        // load X tile (64x32) — float4, coalesced rows
        #pragma unroll
        for (int p = 0; p < 2; p++) {
            int f = tid * 2 + p;          // 0..511
            int m = f >> 3, q = f & 7;
            float4 v = *reinterpret_cast<const float4*>(xblk + (size_t)m * DSPAN + kt + q * 4);
            *reinterpret_cast<float4*>(&Xs[m * 36 + q * 4]) = v;
        }
        // load W1 tile (32x128)
        #pragma unroll
        for (int p = 0; p < 4; p++) {
            int f = tid + p * 256;        // 0..1023
            int kr = f >> 5, h4 = f & 31;
            float4 v = *reinterpret_cast<const float4*>(W1 + (size_t)(kt + kr) * HID + h4 * 4);
            *reinterpret_cast<float4*>(&Ws[kr * HID + h4 * 4]) = v;
        }
        __syncthreads();

        #pragma unroll 8
        for (int kk = 0; kk < 32; kk++) {
            float a0 = Xs[(ty * 4 + 0) * 36 + kk];
            float a1 = Xs[(ty * 4 + 1) * 36 + kk];
            float a2 = Xs[(ty * 4 + 2) * 36 + kk];
            float a3 = Xs[(ty * 4 + 3) * 36 + kk];
            float4 b0 = *reinterpret_cast<const float4*>(&Ws[kk * HID + tx * 8]);
            float4 b1v = *reinterpret_cast<const float4*>(&Ws[kk * HID + tx * 8 + 4]);
            float bv[8] = {b0.x, b0.y, b0.z, b0.w, b1v.x, b1v.y, b1v.z, b1v.w};
            #pragma unroll
            for (int j = 0; j < 8; j++) {
                acc[0][j] += a0 * bv[j];
                acc[1][j] += a1 * bv[j];
                acc[2][j] += a2 * bv[j];
                acc[3][j] += a3 * bv[j];
            }
        }
        __syncthreads();
    }

    // epilogue: relu + bias, dot with W2, reduce over 128 cols
    float part[4] = {0.f, 0.f, 0.f, 0.f};
    #pragma unroll
    for (int j = 0; j < 8; j++) {
        int c = tx * 8 + j;
        float w2 = W2[c], bb = b1[c];
        #pragma unroll
        for (int r = 0; r < 4; r++) {
            float h = fmaxf(acc[r][j] + bb, 0.f);
            part[r] += h * w2;
        }
    }
    #pragma unroll
    for (int r = 0; r < 4; r++) Sred[(ty * 4 + r) * 17 + tx] = part[r];
    __syncthreads();
    if (tid < 64) {
        float s = 0.f;
        #pragma unroll
        for (int t = 0; t < 16; t++) s += Sred[tid * 17 + t];
        int grow = m0 + tid;
        if (grow < N)
            scores[grow] = s + b2[0] + g_width[widx[grow]];
    }
}

// ---------------- radix select: pass 1 histogram (high 16 bits) ----------------
__global__ void k_hist1(const float* __restrict__ scores, int N) {
    int i = blockIdx.x * blockDim.x + threadIdx.x;
    if (i < N) atomicAdd(&g_hist1[f2u(scores[i]) >> 16], 1);
}

__global__ void k_find1(int K) {
    __shared__ int ps[1024];
    int t = threadIdx.x;
    int s = 0;
    for (int i = 0; i < 64; i++) s += g_hist1[t * 64 + i];
    ps[t] = s;
    __syncthreads();
    for (int off = 1; off < 1024; off <<= 1) {
        int add = (t + off < 1024) ? ps[t + off] : 0;
        __syncthreads();
        ps[t] += add;
        __syncthreads();
    }
    int above = (t == 1023) ? 0 : ps[t + 1];
    if (ps[t] >= K && above < K) {
        int cum = above;
        int b = t * 64 + 63;
        for (; b >= t * 64; --b) { cum += g_hist1[b]; if (cum >= K) break; }
        g_b1 = b;
        g_need1 = K - (cum - g_hist1[b]);
    }
}

__global__ void k_hist2(const float* __restrict__ scores, int N) {
    int i = blockIdx.x * blockDim.x + threadIdx.x;
    if (i < N) {
        unsigned u = f2u(scores[i]);
        if ((int)(u >> 16) == g_b1) atomicAdd(&g_hist2[u & 0xFFFFu], 1);
    }
}

__global__ void k_find2() {
    __shared__ int ps[1024];
    int t = threadIdx.x;
    int K = g_need1;
    int s = 0;
    for (int i = 0; i < 64; i++) s += g_hist2[t * 64 + i];
    ps[t] = s;
    __syncthreads();
    for (int off = 1; off < 1024; off <<= 1) {
        int add = (t + off < 1024) ? ps[t + off] : 0;
        __syncthreads();
        ps[t] += add;
        __syncthreads();
    }
    int above = (t == 1023) ? 0 : ps[t + 1];
    if (ps[t] >= K && above < K) {
        int cum = above;
        int b = t * 64 + 63;
        for (; b >= t * 64; --b) { cum += g_hist2[b]; if (cum >= K) break; }
        g_thr = ((unsigned)g_b1 << 16) | (unsigned)b;
        g_needeq = K - (cum - g_hist2[b]);
    }
}

// ---------------- tie handling (lowest-index ties, matching lax.top_k) ----------------
__global__ void k_tie(const float* __restrict__ scores, int N) {
    int i = blockIdx.x * blockDim.x + threadIdx.x;
    if (i < N && f2u(scores[i]) == g_thr) {
        int p = atomicAdd(&g_tiecnt, 1);
        if (p < 1024) g_tie[p] = i;
    }
}

__global__ void k_tiesel() {
    if (threadIdx.x != 0) return;
    int need = g_needeq;
    int cnt = min(g_tiecnt, 1024);
    if (need >= cnt) { g_cutoff = 0x7FFFFFFF; return; }
    int last = -1;
    for (int it = 0; it < need; it++) {
        int best = 0x7FFFFFFF;
        for (int j = 0; j < cnt; j++) {
            int v = g_tie[j];
            if (v > last && v < best) best = v;
        }
        last = best;
    }
    g_cutoff = last;  // need==0 -> -1 (no ties included)
}

// ---------------- ordered compaction: count / scan / scatter ----------------
__global__ void k_count(const float* __restrict__ scores, int N) {
    int t = threadIdx.x;
    unsigned thr = g_thr;
    int cut = g_cutoff;
    int base = blockIdx.x * 4096 + t * 4;
    int c = 0;
    #pragma unroll
    for (int e = 0; e < 4; e++) {
        int i = base + e;
        if (i < N && sel_pred(f2u(scores[i]), i, thr, cut)) c++;
    }
    // block reduce
    for (int off = 16; off > 0; off >>= 1) c += __shfl_down_sync(0xFFFFFFFFu, c, off);
    __shared__ int red[32];
    if ((t & 31) == 0) red[t >> 5] = c;
    __syncthreads();
    if (t < 32) {
        int v = red[t];
        for (int off = 16; off > 0; off >>= 1) v += __shfl_down_sync(0xFFFFFFFFu, v, off);
        if (t == 0) g_bcnt[blockIdx.x] = v;
    }
}

__global__ void k_scanb(int nb) {
    __shared__ int s[256];
    int t = threadIdx.x;
    int v = (t < nb) ? g_bcnt[t] : 0;
    s[t] = v;
    __syncthreads();
    for (int off = 1; off < 256; off <<= 1) {
        int add = (t >= off) ? s[t - off] : 0;
        __syncthreads();
        s[t] += add;
        __syncthreads();
    }
    g_boff[t] = s[t] - v;  // exclusive prefix
}

__global__ void k_scatter(const float* __restrict__ scores,
                          const int* __restrict__ beg, const int* __restrict__ end, int N,
                          float* __restrict__ o_ti, float* __restrict__ o_sc,
                          float* __restrict__ o_bg, float* __restrict__ o_en) {
    __shared__ int s[1024];
    int t = threadIdx.x;
    unsigned thr = g_thr;
    int cut = g_cutoff;
    int base = blockIdx.x * 4096 + t * 4;
    bool f[4];
    int c = 0;
    #pragma unroll
    for (int e = 0; e < 4; e++) {
        int i = base + e;
        f[e] = (i < N) && sel_pred(f2u(scores[i]), i, thr, cut);
        c += f[e] ? 1 : 0;
    }
    s[t] = c;
    __syncthreads();
    for (int off = 1; off < 1024; off <<= 1) {
        int add = (t >= off) ? s[t - off] : 0;
        __syncthreads();
        s[t] += add;
        __syncthreads();
    }
    int pos = g_boff[blockIdx.x] + s[t] - c;  // exclusive in-block prefix
    #pragma unroll
    for (int e = 0; e < 4; e++) {
        if (f[e]) {
            int i = base + e;
            g_topi[pos] = i;
            o_ti[pos] = (float)i;
            o_sc[pos] = scores[i];
            o_bg[pos] = (float)beg[i];
            o_en[pos] = (float)end[i];
            pos++;
        }
    }
}

// ---------------- gather selected span vectors ----------------
__global__ void k_gather(const float* __restrict__ x, float* __restrict__ out) {
    int r = blockIdx.x;
    int src = g_topi[r];
    const float4* s = reinterpret_cast<const float4*>(x + (size_t)src * DSPAN);
    float4* d = reinterpret_cast<float4*>(out + (size_t)r * DSPAN);
    d[threadIdx.x] = s[threadIdx.x];
}

// ---------------- launch ----------------
extern "C" void kernel_launch(void* const* d_in, const int* in_sizes, int n_in,
                              void* d_out, int out_size) {
    const float* x    = (const float*)d_in[0];
    const int*   cbeg = (const int*)d_in[1];
    const int*   cend = (const int*)d_in[2];
    const int*   cwid = (const int*)d_in[3];
    const float* wemb = (const float*)d_in[4];
    const float* W1   = (const float*)d_in[5];
    const float* b1   = (const float*)d_in[6];
    const float* W2   = (const float*)d_in[7];
    const float* b2   = (const float*)d_in[8];
    const float* Ww1  = (const float*)d_in[9];
    const float* bw1  = (const float*)d_in[10];
    const float* Ww2  = (const float*)d_in[11];
    const float* bw2  = (const float*)d_in[12];

    int N = in_sizes[1];                 // 262144
    int D = in_sizes[0] / N;             // 1024
    int k = (out_size - N) / (D + 4);    // 3276

    float* out     = (float*)d_out;
    float* o_prune = out;                        // [N]
    float* o_vecs  = out + N;                    // [k, D]
    float* o_sc    = o_vecs + (size_t)k * D;     // [k]
    float* o_bg    = o_sc + k;                   // [k]
    float* o_en    = o_bg + k;                   // [k]
    float* o_ti    = o_en + k;                   // [k]

    k_setup<<<512, 256>>>();
    k_width<<<1, 128>>>(wemb, Ww1, bw1, Ww2, bw2);
    k_gemm<<<N / 64, 256>>>(x, W1, b1, W2, b2, cwid, o_prune, N);

    int nthr = (N + 255) / 256;
    k_hist1<<<nthr, 256>>>(o_prune, N);
    k_find1<<<1, 1024>>>(k);
    k_hist2<<<nthr, 256>>>(o_prune, N);
    k_find2<<<1, 1024>>>();
    k_tie<<<nthr, 256>>>(o_prune, N);
    k_tiesel<<<1, 32>>>();

    int nb = (N + 4095) / 4096;          // 64
    k_count<<<nb, 1024>>>(o_prune, N);
    k_scanb<<<1, 256>>>(nb);
    k_scatter<<<nb, 1024>>>(o_prune, cbeg, cend, N, o_ti, o_sc, o_bg, o_en);

    k_gather<<<k, 256>>>(x, o_vecs);
}

// round 4
// speedup vs baseline: 2.4847x; 2.4847x over previous
#include <cuda_runtime.h>
#include <cuda_bf16.h>
#include <cstdint>

#define DSPAN 1024
#define HID   128
#define FEAT  20
#define NWID  30

// ======================= device scratch =======================
__device__ int      g_hist1[65536];
__device__ int      g_hist2[65536];
__device__ int      g_b1, g_need1, g_needeq, g_tiecnt, g_cutoff, g_nband;
__device__ unsigned g_thr;
__device__ float    g_vlo, g_vhi;
__device__ int      g_tie[1024];
__device__ int      g_bcnt[256];
__device__ int      g_boff[256];
__device__ int      g_topi[4096];
__device__ float    g_width[32];
__device__ int      g_band[131072];
// W1 transposed [H][D], split hi/lo bf16
__device__ __align__(16) __nv_bfloat16 g_w1t_hi[HID * DSPAN];
__device__ __align__(16) __nv_bfloat16 g_w1t_lo[HID * DSPAN];

__device__ __forceinline__ unsigned f2u(float f) {
    unsigned b = __float_as_uint(f);
    return b ^ ((unsigned)((int)b >> 31) | 0x80000000u);
}
__device__ __forceinline__ float u2f(unsigned u) {
    unsigned b = (u & 0x80000000u) ? (u ^ 0x80000000u) : ~u;
    return __uint_as_float(b);
}
__device__ __forceinline__ bool sel_pred(unsigned u, int i, unsigned thr, int cut) {
    return (u > thr) || (u == thr && i <= cut);
}
__device__ __forceinline__ uint32_t smem_u32(const void* p) {
    uint32_t a;
    asm("{ .reg .u64 t; cvta.to.shared.u64 t, %1; cvt.u32.u64 %0, t; }" : "=r"(a) : "l"(p));
    return a;
}
__device__ __forceinline__ void ldm_x4(uint32_t& r0, uint32_t& r1, uint32_t& r2, uint32_t& r3, uint32_t a) {
    asm volatile("ldmatrix.sync.aligned.m8n8.x4.shared.b16 {%0,%1,%2,%3}, [%4];"
                 : "=r"(r0), "=r"(r1), "=r"(r2), "=r"(r3) : "r"(a));
}
__device__ __forceinline__ void mma_bf16(float* d, const uint32_t* a, uint32_t b0, uint32_t b1) {
    asm volatile(
        "mma.sync.aligned.m16n8k16.row.col.f32.bf16.bf16.f32 "
        "{%0,%1,%2,%3}, {%4,%5,%6,%7}, {%8,%9}, {%0,%1,%2,%3};"
        : "+f"(d[0]), "+f"(d[1]), "+f"(d[2]), "+f"(d[3])
        : "r"(a[0]), "r"(a[1]), "r"(a[2]), "r"(a[3]), "r"(b0), "r"(b1));
}
__device__ __forceinline__ unsigned pack_bf2(__nv_bfloat16 a, __nv_bfloat16 b) {
    return (unsigned)__bfloat16_as_ushort(a) | ((unsigned)__bfloat16_as_ushort(b) << 16);
}

// ======================= setup =======================
__global__ void k_setup() {
    int i = blockIdx.x * blockDim.x + threadIdx.x;
    if (i < 65536) g_hist1[i] = 0;
    int j = i - 65536;
    if (j >= 0 && j < 65536) g_hist2[j] = 0;
    if (i == 0) g_tiecnt = 0;
    if (i == 1) g_nband = 0;
}

// ======================= width prior =======================
__global__ void k_width(const float* __restrict__ emb,
                        const float* __restrict__ Ww1, const float* __restrict__ bw1,
                        const float* __restrict__ Ww2, const float* __restrict__ bw2) {
    __shared__ float red[128];
    int j = threadIdx.x;
    for (int w = 0; w < NWID; w++) {
        float acc = bw1[j];
        #pragma unroll
        for (int kk = 0; kk < FEAT; kk++)
            acc += emb[w * FEAT + kk] * Ww1[kk * HID + j];
        red[j] = fmaxf(acc, 0.f) * Ww2[j];
        __syncthreads();
        for (int s = 64; s > 0; s >>= 1) {
            if (j < s) red[j] += red[j + s];
            __syncthreads();
        }
        if (j == 0) g_width[w] = red[0] + bw2[0];
        __syncthreads();
    }
}

// ======================= W1 split + transpose =======================
__global__ void k_splitw(const float* __restrict__ W1) {
    int i = blockIdx.x * blockDim.x + threadIdx.x;
    if (i < DSPAN * HID) {
        int kk = i >> 7, n = i & 127;
        float v = W1[i];
        __nv_bfloat16 h = __float2bfloat16(v);
        __nv_bfloat16 l = __float2bfloat16(v - __bfloat162float(h));
        g_w1t_hi[n * DSPAN + kk] = h;
        g_w1t_lo[n * DSPAN + kk] = l;
    }
}

// ======================= bf16x3 warp-MMA GEMM + fused epilogue =======================
// CTA: 128 rows x 128 cols (full H). 8 warps = 4(M) x 2(N), warp tile 32x64.
// K chunked by 32, smem rows padded to 40 elems (80B) for conflict-free ldmatrix.
#define SA 40
__global__ __launch_bounds__(256, 2)
void k_gemm_mma(const float* __restrict__ x,
                const float* __restrict__ b1, const float* __restrict__ W2,
                const float* __restrict__ b2, const int* __restrict__ widx,
                float* __restrict__ scores, int N) {
    __shared__ __align__(16) __nv_bfloat16 sAh[128 * SA];
    __shared__ __align__(16) __nv_bfloat16 sAl[128 * SA];
    __shared__ __align__(16) __nv_bfloat16 sBh[128 * SA];
    __shared__ __align__(16) __nv_bfloat16 sBl[128 * SA];
    __shared__ float sb1[128], sw2[128];
    __shared__ float sred[2][128];

    int tid = threadIdx.x;
    int wid = tid >> 5, lid = tid & 31;
    int warp_m = wid & 3, warp_n = wid >> 2;      // 4 x 2
    int wm = warp_m * 32, wn = warp_n * 64;
    int gid = lid >> 2, tig = lid & 3;
    int m0 = blockIdx.x * 128;

    if (tid < 128) { sb1[tid] = b1[tid]; sw2[tid] = W2[tid]; }

    float acc[2][8][4];
    #pragma unroll
    for (int mt = 0; mt < 2; mt++)
        #pragma unroll
        for (int nt = 0; nt < 8; nt++)
            #pragma unroll
            for (int q = 0; q < 4; q++) acc[mt][nt][q] = 0.f;

    const float* xblk = x + (size_t)m0 * DSPAN;
    uint32_t uAh = smem_u32(sAh), uAl = smem_u32(sAl);
    uint32_t uBh = smem_u32(sBh), uBl = smem_u32(sBl);

    // precompute ldmatrix lane addressing
    int a_row = (lid & 15);                         // + wm + mt*16
    int a_kk  = (lid >> 4) << 3;                    // 0 or 8 (+ s*16)
    int b_row = (lid & 7) + ((lid & 16) ? 8 : 0);   // + wn + np*16
    int b_kk  = (lid & 8);                          // 0 or 8 (+ s*16)

    for (int ch = 0; ch < 32; ch++) {
        int kt = ch * 32;
        // ---- A tile: 128 x 32 fp32 -> hi/lo bf16 ----
        #pragma unroll
        for (int p = 0; p < 4; p++) {
            int g = tid + p * 256;        // 0..1023 float4 units
            int row = g >> 3, c4 = g & 7;
            float4 v = *reinterpret_cast<const float4*>(xblk + (size_t)row * DSPAN + kt + c4 * 4);
            __nv_bfloat16 h0 = __float2bfloat16(v.x), h1 = __float2bfloat16(v.y);
            __nv_bfloat16 h2 = __float2bfloat16(v.z), h3 = __float2bfloat16(v.w);
            __nv_bfloat16 l0 = __float2bfloat16(v.x - __bfloat162float(h0));
            __nv_bfloat16 l1 = __float2bfloat16(v.y - __bfloat162float(h1));
            __nv_bfloat16 l2 = __float2bfloat16(v.z - __bfloat162float(h2));
            __nv_bfloat16 l3 = __float2bfloat16(v.w - __bfloat162float(h3));
            int off = row * SA + c4 * 4;
            *reinterpret_cast<uint2*>(&sAh[off]) = make_uint2(pack_bf2(h0, h1), pack_bf2(h2, h3));
            *reinterpret_cast<uint2*>(&sAl[off]) = make_uint2(pack_bf2(l0, l1), pack_bf2(l2, l3));
        }
        // ---- B tiles: W1T hi/lo, 128 n x 32 k bf16 ----
        #pragma unroll
        for (int p = 0; p < 2; p++) {
            int g = tid + p * 256;        // 0..511 uint4 units (8 bf16)
            int row = g >> 2, c8 = g & 3;
            uint4 vh = *reinterpret_cast<const uint4*>(&g_w1t_hi[(size_t)row * DSPAN + kt + c8 * 8]);
            uint4 vl = *reinterpret_cast<const uint4*>(&g_w1t_lo[(size_t)row * DSPAN + kt + c8 * 8]);
            int off = row * SA + c8 * 8;
            *reinterpret_cast<uint4*>(&sBh[off]) = vh;
            *reinterpret_cast<uint4*>(&sBl[off]) = vl;
        }
        __syncthreads();

        #pragma unroll
        for (int s = 0; s < 2; s++) {
            uint32_t ah[2][4], al[2][4];
            #pragma unroll
            for (int mt = 0; mt < 2; mt++) {
                uint32_t aoff = (uint32_t)(((wm + mt * 16 + a_row) * SA + s * 16 + a_kk) * 2);
                ldm_x4(ah[mt][0], ah[mt][1], ah[mt][2], ah[mt][3], uAh + aoff);
                ldm_x4(al[mt][0], al[mt][1], al[mt][2], al[mt][3], uAl + aoff);
            }
            #pragma unroll
            for (int np = 0; np < 4; np++) {
                uint32_t boff = (uint32_t)(((wn + np * 16 + b_row) * SA + s * 16 + b_kk) * 2);
                uint32_t bh0, bh1, bh2, bh3, bl0, bl1, bl2, bl3;
                ldm_x4(bh0, bh1, bh2, bh3, uBh + boff);
                ldm_x4(bl0, bl1, bl2, bl3, uBl + boff);
                #pragma unroll
                for (int mt = 0; mt < 2; mt++) {
                    mma_bf16(acc[mt][np * 2],     ah[mt], bh0, bh1);
                    mma_bf16(acc[mt][np * 2 + 1], ah[mt], bh2, bh3);
                    mma_bf16(acc[mt][np * 2],     ah[mt], bl0, bl1);
                    mma_bf16(acc[mt][np * 2 + 1], ah[mt], bl2, bl3);
                    mma_bf16(acc[mt][np * 2],     al[mt], bh0, bh1);
                    mma_bf16(acc[mt][np * 2 + 1], al[mt], bh2, bh3);
                }
            }
        }
        __syncthreads();
    }

    // ---- fused epilogue: relu + bias, dot W2, reduce ----
    #pragma unroll
    for (int mt = 0; mt < 2; mt++) {
        #pragma unroll
        for (int h = 0; h < 2; h++) {
            float s = 0.f;
            #pragma unroll
            for (int nt = 0; nt < 8; nt++) {
                int col = wn + nt * 8 + tig * 2;
                float v0 = acc[mt][nt][h * 2 + 0] + sb1[col];
                float v1 = acc[mt][nt][h * 2 + 1] + sb1[col + 1];
                s += fmaxf(v0, 0.f) * sw2[col] + fmaxf(v1, 0.f) * sw2[col + 1];
            }
            s += __shfl_xor_sync(0xFFFFFFFFu, s, 1);
            s += __shfl_xor_sync(0xFFFFFFFFu, s, 2);
            if (tig == 0) sred[warp_n][wm + mt * 16 + h * 8 + gid] = s;
        }
    }
    __syncthreads();
    if (tid < 128) {
        int row = m0 + tid;
        if (row < N)
            scores[row] = sred[0][tid] + sred[1][tid] + b2[0] + g_width[widx[row]];
    }
}

// ======================= radix select =======================
__global__ void k_hist1(const float* __restrict__ scores, int N) {
    int i = blockIdx.x * blockDim.x + threadIdx.x;
    if (i < N) atomicAdd(&g_hist1[f2u(scores[i]) >> 16], 1);
}

__global__ void k_find1(int K) {
    __shared__ int ps[1024];
    int t = threadIdx.x;
    int s = 0;
    for (int i = 0; i < 64; i++) s += g_hist1[t * 64 + i];
    ps[t] = s;
    __syncthreads();
    for (int off = 1; off < 1024; off <<= 1) {
        int add = (t + off < 1024) ? ps[t + off] : 0;
        __syncthreads();
        ps[t] += add;
        __syncthreads();
    }
    int above = (t == 1023) ? 0 : ps[t + 1];
    if (ps[t] >= K && above < K) {
        int cum = above;
        int b = t * 64 + 63;
        for (; b >= t * 64; --b) { cum += g_hist1[b]; if (cum >= K) break; }
        g_b1 = b;
        g_need1 = K - (cum - g_hist1[b]);
        g_vlo = u2f((unsigned)b << 16);
        g_vhi = u2f(((unsigned)b << 16) | 0xFFFFu);
    }
}

// ---- band repair: exact fp32 recompute near the threshold bucket ----
__global__ void k_bandlist(const float* __restrict__ scores, int N) {
    int i = blockIdx.x * blockDim.x + threadIdx.x;
    if (i < N) {
        float s = scores[i];
        float lo = fminf(g_vlo, g_vhi), hi = fmaxf(g_vlo, g_vhi);
        if (s >= lo - 1e-4f && s <= hi + 1e-4f) {
            int p = atomicAdd(&g_nband, 1);
            if (p < 131072) g_band[p] = i;
        }
    }
}

__global__ void k_exact(const float* __restrict__ x,
                        const float* __restrict__ W1, const float* __restrict__ b1,
                        const float* __restrict__ W2, const float* __restrict__ b2,
                        const int* __restrict__ widx, float* __restrict__ scores) {
    __shared__ float xs[1024];
    __shared__ float red[128];
    int nb = min(g_nband, 131072);
    int j = threadIdx.x;
    for (int it = blockIdx.x; it < nb; it += gridDim.x) {
        int i = g_band[it];
        for (int t = j; t < 1024; t += 128) xs[t] = x[(size_t)i * DSPAN + t];
        __syncthreads();
        float acc = b1[j];
        #pragma unroll 8
        for (int kk = 0; kk < 1024; kk++) acc += xs[kk] * W1[kk * HID + j];
        red[j] = fmaxf(acc, 0.f) * W2[j];
        __syncthreads();
        for (int s = 64; s > 0; s >>= 1) {
            if (j < s) red[j] += red[j + s];
            __syncthreads();
        }
        if (j == 0) scores[i] = red[0] + b2[0] + g_width[widx[i]];
        __syncthreads();
    }
}

__global__ void k_hist2(const float* __restrict__ scores, int N) {
    int i = blockIdx.x * blockDim.x + threadIdx.x;
    if (i < N) {
        unsigned u = f2u(scores[i]);
        if ((int)(u >> 16) == g_b1) atomicAdd(&g_hist2[u & 0xFFFFu], 1);
    }
}

__global__ void k_find2() {
    __shared__ int ps[1024];
    int t = threadIdx.x;
    int K = g_need1;
    int s = 0;
    for (int i = 0; i < 64; i++) s += g_hist2[t * 64 + i];
    ps[t] = s;
    __syncthreads();
    for (int off = 1; off < 1024; off <<= 1) {
        int add = (t + off < 1024) ? ps[t + off] : 0;
        __syncthreads();
        ps[t] += add;
        __syncthreads();
    }
    int above = (t == 1023) ? 0 : ps[t + 1];
    if (ps[t] >= K && above < K) {
        int cum = above;
        int b = t * 64 + 63;
        for (; b >= t * 64; --b) { cum += g_hist2[b]; if (cum >= K) break; }
        g_thr = ((unsigned)g_b1 << 16) | (unsigned)b;
        g_needeq = K - (cum - g_hist2[b]);
    }
}

__global__ void k_tie(const float* __restrict__ scores, int N) {
    int i = blockIdx.x * blockDim.x + threadIdx.x;
    if (i < N && f2u(scores[i]) == g_thr) {
        int p = atomicAdd(&g_tiecnt, 1);
        if (p < 1024) g_tie[p] = i;
    }
}

__global__ void k_tiesel() {
    if (threadIdx.x != 0) return;
    int need = g_needeq;
    int cnt = min(g_tiecnt, 1024);
    if (need >= cnt) { g_cutoff = 0x7FFFFFFF; return; }
    int last = -1;
    for (int it = 0; it < need; it++) {
        int best = 0x7FFFFFFF;
        for (int j = 0; j < cnt; j++) {
            int v = g_tie[j];
            if (v > last && v < best) best = v;
        }
        last = best;
    }
    g_cutoff = last;
}

// ======================= ordered compaction =======================
__global__ void k_count(const float* __restrict__ scores, int N) {
    int t = threadIdx.x;
    unsigned thr = g_thr;
    int cut = g_cutoff;
    int base = blockIdx.x * 4096 + t * 4;
    int c = 0;
    #pragma unroll
    for (int e = 0; e < 4; e++) {
        int i = base + e;
        if (i < N && sel_pred(f2u(scores[i]), i, thr, cut)) c++;
    }
    for (int off = 16; off > 0; off >>= 1) c += __shfl_down_sync(0xFFFFFFFFu, c, off);
    __shared__ int red[32];
    if ((t & 31) == 0) red[t >> 5] = c;
    __syncthreads();
    if (t < 32) {
        int v = red[t];
        for (int off = 16; off > 0; off >>= 1) v += __shfl_down_sync(0xFFFFFFFFu, v, off);
        if (t == 0) g_bcnt[blockIdx.x] = v;
    }
}

__global__ void k_scanb(int nb) {
    __shared__ int s[256];
    int t = threadIdx.x;
    int v = (t < nb) ? g_bcnt[t] : 0;
    s[t] = v;
    __syncthreads();
    for (int off = 1; off < 256; off <<= 1) {
        int add = (t >= off) ? s[t - off] : 0;
        __syncthreads();
        s[t] += add;
        __syncthreads();
    }
    g_boff[t] = s[t] - v;
}

__global__ void k_scatter(const float* __restrict__ scores,
                          const int* __restrict__ beg, const int* __restrict__ end, int N,
                          float* __restrict__ o_ti, float* __restrict__ o_sc,
                          float* __restrict__ o_bg, float* __restrict__ o_en) {
    __shared__ int s[1024];
    int t = threadIdx.x;
    unsigned thr = g_thr;
    int cut = g_cutoff;
    int base = blockIdx.x * 4096 + t * 4;
    bool f[4];
    int c = 0;
    #pragma unroll
    for (int e = 0; e < 4; e++) {
        int i = base + e;
        f[e] = (i < N) && sel_pred(f2u(scores[i]), i, thr, cut);
        c += f[e] ? 1 : 0;
    }
    s[t] = c;
    __syncthreads();
    for (int off = 1; off < 1024; off <<= 1) {
        int add = (t >= off) ? s[t - off] : 0;
        __syncthreads();
        s[t] += add;
        __syncthreads();
    }
    int pos = g_boff[blockIdx.x] + s[t] - c;
    #pragma unroll
    for (int e = 0; e < 4; e++) {
        if (f[e]) {
            int i = base + e;
            g_topi[pos] = i;
            o_ti[pos] = (float)i;
            o_sc[pos] = scores[i];
            o_bg[pos] = (float)beg[i];
            o_en[pos] = (float)end[i];
            pos++;
        }
    }
}

__global__ void k_gather(const float* __restrict__ x, float* __restrict__ out) {
    int r = blockIdx.x;
    int src = g_topi[r];
    const float4* s = reinterpret_cast<const float4*>(x + (size_t)src * DSPAN);
    float4* d = reinterpret_cast<float4*>(out + (size_t)r * DSPAN);
    d[threadIdx.x] = s[threadIdx.x];
}

// ======================= launch =======================
extern "C" void kernel_launch(void* const* d_in, const int* in_sizes, int n_in,
                              void* d_out, int out_size) {
    const float* x    = (const float*)d_in[0];
    const int*   cbeg = (const int*)d_in[1];
    const int*   cend = (const int*)d_in[2];
    const int*   cwid = (const int*)d_in[3];
    const float* wemb = (const float*)d_in[4];
    const float* W1   = (const float*)d_in[5];
    const float* b1   = (const float*)d_in[6];
    const float* W2   = (const float*)d_in[7];
    const float* b2   = (const float*)d_in[8];
    const float* Ww1  = (const float*)d_in[9];
    const float* bw1  = (const float*)d_in[10];
    const float* Ww2  = (const float*)d_in[11];
    const float* bw2  = (const float*)d_in[12];

    int N = in_sizes[1];                 // 262144
    int D = in_sizes[0] / N;             // 1024
    int k = (out_size - N) / (D + 4);    // 3276

    float* out     = (float*)d_out;
    float* o_prune = out;                        // [N]
    float* o_vecs  = out + N;                    // [k, D]
    float* o_sc    = o_vecs + (size_t)k * D;     // [k]
    float* o_bg    = o_sc + k;                   // [k]
    float* o_en    = o_bg + k;                   // [k]
    float* o_ti    = o_en + k;                   // [k]

    k_setup<<<512, 256>>>();
    k_width<<<1, 128>>>(wemb, Ww1, bw1, Ww2, bw2);
    k_splitw<<<(DSPAN * HID + 255) / 256, 256>>>(W1);

    k_gemm_mma<<<N / 128, 256>>>(x, b1, W2, b2, cwid, o_prune, N);

    int nthr = (N + 255) / 256;
    // pass A: locate threshold bucket on approx scores, repair band exactly
    k_hist1<<<nthr, 256>>>(o_prune, N);
    k_find1<<<1, 1024>>>(k);
    k_bandlist<<<nthr, 256>>>(o_prune, N);
    k_exact<<<512, 128>>>(x, W1, b1, W2, b2, cwid, o_prune);

    // pass B: exact selection on repaired scores
    k_setup<<<512, 256>>>();
    k_hist1<<<nthr, 256>>>(o_prune, N);
    k_find1<<<1, 1024>>>(k);
    k_hist2<<<nthr, 256>>>(o_prune, N);
    k_find2<<<1, 1024>>>();
    k_tie<<<nthr, 256>>>(o_prune, N);
    k_tiesel<<<1, 32>>>();

    int nb = (N + 4095) / 4096;          // 64
    k_count<<<nb, 1024>>>(o_prune, N);
    k_scanb<<<1, 256>>>(nb);
    k_scatter<<<nb, 1024>>>(o_prune, cbeg, cend, N, o_ti, o_sc, o_bg, o_en);

    k_gather<<<k, 256>>>(x, o_vecs);
}

// round 5
// speedup vs baseline: 2.7283x; 1.0981x over previous
#include <cuda_runtime.h>
#include <cuda_fp16.h>
#include <cstdint>

#define DSPAN 1024
#define HID   128
#define FEAT  20
#define NWID  30
#define MARGIN 16384u

// ======================= device scratch =======================
__device__ int      g_h8a[256];
__device__ int      g_h8b[256];
__device__ int      g_bhi, g_needA;
__device__ unsigned g_lou, g_hiu;
__device__ int      g_nband, g_cabove;
__device__ unsigned g_thru;
__device__ int      g_cut;
__device__ int      g_bcnt[256];
__device__ int      g_boff[256];
__device__ int      g_topi[4096];
__device__ float    g_width[32];
__device__ int      g_band[65536];
// W1 transposed [H][D], split hi/lo fp16
__device__ __align__(16) __half g_w1t_hi[HID * DSPAN];
__device__ __align__(16) __half g_w1t_lo[HID * DSPAN];

__device__ __forceinline__ unsigned f2u(float f) {
    unsigned b = __float_as_uint(f);
    return b ^ ((unsigned)((int)b >> 31) | 0x80000000u);
}
__device__ __forceinline__ bool sel_pred(unsigned u, int i, unsigned thr, int cut) {
    return (u > thr) || (u == thr && i <= cut);
}
__device__ __forceinline__ uint32_t smem_u32(const void* p) {
    uint32_t a;
    asm("{ .reg .u64 t; cvta.to.shared.u64 t, %1; cvt.u32.u64 %0, t; }" : "=r"(a) : "l"(p));
    return a;
}
__device__ __forceinline__ void ldm_x4(uint32_t& r0, uint32_t& r1, uint32_t& r2, uint32_t& r3, uint32_t a) {
    asm volatile("ldmatrix.sync.aligned.m8n8.x4.shared.b16 {%0,%1,%2,%3}, [%4];"
                 : "=r"(r0), "=r"(r1), "=r"(r2), "=r"(r3) : "r"(a));
}
__device__ __forceinline__ void mma_f16(float* d, const uint32_t* a, uint32_t b0, uint32_t b1) {
    asm volatile(
        "mma.sync.aligned.m16n8k16.row.col.f32.f16.f16.f32 "
        "{%0,%1,%2,%3}, {%4,%5,%6,%7}, {%8,%9}, {%0,%1,%2,%3};"
        : "+f"(d[0]), "+f"(d[1]), "+f"(d[2]), "+f"(d[3])
        : "r"(a[0]), "r"(a[1]), "r"(a[2]), "r"(a[3]), "r"(b0), "r"(b1));
}
__device__ __forceinline__ unsigned pack_h2(__half a, __half b) {
    return (unsigned)__half_as_ushort(a) | ((unsigned)__half_as_ushort(b) << 16);
}

// ======================= setup =======================
__global__ void k_setup() {
    int i = threadIdx.x;
    if (i < 256) { g_h8a[i] = 0; g_h8b[i] = 0; }
    if (i == 0) { g_nband = 0; g_cabove = 0; }
}

// ======================= width prior =======================
__global__ void k_width(const float* __restrict__ emb,
                        const float* __restrict__ Ww1, const float* __restrict__ bw1,
                        const float* __restrict__ Ww2, const float* __restrict__ bw2) {
    __shared__ float red[128];
    int j = threadIdx.x;
    for (int w = 0; w < NWID; w++) {
        float acc = bw1[j];
        #pragma unroll
        for (int kk = 0; kk < FEAT; kk++)
            acc += emb[w * FEAT + kk] * Ww1[kk * HID + j];
        red[j] = fmaxf(acc, 0.f) * Ww2[j];
        __syncthreads();
        for (int s = 64; s > 0; s >>= 1) {
            if (j < s) red[j] += red[j + s];
            __syncthreads();
        }
        if (j == 0) g_width[w] = red[0] + bw2[0];
        __syncthreads();
    }
}

// ======================= W1 split + transpose (fp16) =======================
__global__ void k_splitw(const float* __restrict__ W1) {
    int i = blockIdx.x * blockDim.x + threadIdx.x;
    if (i < DSPAN * HID) {
        int kk = i >> 7, n = i & 127;
        float v = W1[i];
        __half h = __float2half_rn(v);
        __half l = __float2half_rn(v - __half2float(h));
        g_w1t_hi[n * DSPAN + kk] = h;
        g_w1t_lo[n * DSPAN + kk] = l;
    }
}

// ======================= fp16x3 warp-MMA GEMM, reg-prefetch pipelined =======================
// CTA: 128 rows x 128 cols (full H). 8 warps = 4(M) x 2(N), warp tile 32x64.
// K chunked by 32, smem rows padded to 40 elems (80B) for conflict-free ldmatrix.
#define SA 40
__global__ __launch_bounds__(256)
void k_gemm_mma(const float* __restrict__ x,
                const float* __restrict__ b1, const float* __restrict__ W2,
                const float* __restrict__ b2, const int* __restrict__ widx,
                float* __restrict__ scores, int N) {
    __shared__ __align__(16) __half sAh[128 * SA];
    __shared__ __align__(16) __half sAl[128 * SA];
    __shared__ __align__(16) __half sBh[128 * SA];
    __shared__ __align__(16) __half sBl[128 * SA];
    __shared__ float sb1[128], sw2[128];
    __shared__ float sred[2][128];

    int tid = threadIdx.x;
    int wid = tid >> 5, lid = tid & 31;
    int warp_m = wid & 3, warp_n = wid >> 2;      // 4 x 2
    int wm = warp_m * 32, wn = warp_n * 64;
    int gid = lid >> 2, tig = lid & 3;
    int m0 = blockIdx.x * 128;

    if (tid < 128) { sb1[tid] = b1[tid]; sw2[tid] = W2[tid]; }

    float acc[2][8][4];
    #pragma unroll
    for (int mt = 0; mt < 2; mt++)
        #pragma unroll
        for (int nt = 0; nt < 8; nt++)
            #pragma unroll
            for (int q = 0; q < 4; q++) acc[mt][nt][q] = 0.f;

    const float* xblk = x + (size_t)m0 * DSPAN;
    uint32_t uAh = smem_u32(sAh), uAl = smem_u32(sAl);
    uint32_t uBh = smem_u32(sBh), uBl = smem_u32(sBl);

    int a_row = (lid & 15);
    int a_kk  = (lid >> 4) << 3;
    int b_row = (lid & 7) + ((lid & 16) ? 8 : 0);
    int b_kk  = (lid & 8);

    // prefetch registers
    float4 aR[4];
    uint4  bhR[2], blR[2];

    auto load_tile = [&](int ch) {
        int kt = ch * 32;
        #pragma unroll
        for (int p = 0; p < 4; p++) {
            int g = p * 256 + tid;
            int row = g >> 3, c4 = g & 7;
            aR[p] = *reinterpret_cast<const float4*>(xblk + (size_t)row * DSPAN + kt + c4 * 4);
        }
        #pragma unroll
        for (int p = 0; p < 2; p++) {
            int g = p * 256 + tid;
            int row = g >> 2, c8 = g & 3;
            bhR[p] = *reinterpret_cast<const uint4*>(&g_w1t_hi[(size_t)row * DSPAN + kt + c8 * 8]);
            blR[p] = *reinterpret_cast<const uint4*>(&g_w1t_lo[(size_t)row * DSPAN + kt + c8 * 8]);
        }
    };
    auto store_tile = [&]() {
        #pragma unroll
        for (int p = 0; p < 4; p++) {
            int g = p * 256 + tid;
            int row = g >> 3, c4 = g & 7;
            float4 v = aR[p];
            __half h0 = __float2half_rn(v.x), h1 = __float2half_rn(v.y);
            __half h2 = __float2half_rn(v.z), h3 = __float2half_rn(v.w);
            __half l0 = __float2half_rn(v.x - __half2float(h0));
            __half l1 = __float2half_rn(v.y - __half2float(h1));
            __half l2 = __float2half_rn(v.z - __half2float(h2));
            __half l3 = __float2half_rn(v.w - __half2float(h3));
            int off = row * SA + c4 * 4;
            *reinterpret_cast<uint2*>(&sAh[off]) = make_uint2(pack_h2(h0, h1), pack_h2(h2, h3));
            *reinterpret_cast<uint2*>(&sAl[off]) = make_uint2(pack_h2(l0, l1), pack_h2(l2, l3));
        }
        #pragma unroll
        for (int p = 0; p < 2; p++) {
            int g = p * 256 + tid;
            int row = g >> 2, c8 = g & 3;
            int off = row * SA + c8 * 8;
            *reinterpret_cast<uint4*>(&sBh[off]) = bhR[p];
            *reinterpret_cast<uint4*>(&sBl[off]) = blR[p];
        }
    };

    load_tile(0);

    for (int ch = 0; ch < 32; ch++) {
        store_tile();
        __syncthreads();
        if (ch < 31) load_tile(ch + 1);   // LDGs fly during the MMA section

        #pragma unroll
        for (int s = 0; s < 2; s++) {
            uint32_t ah[2][4], al[2][4];
            #pragma unroll
            for (int mt = 0; mt < 2; mt++) {
                uint32_t aoff = (uint32_t)(((wm + mt * 16 + a_row) * SA + s * 16 + a_kk) * 2);
                ldm_x4(ah[mt][0], ah[mt][1], ah[mt][2], ah[mt][3], uAh + aoff);
                ldm_x4(al[mt][0], al[mt][1], al[mt][2], al[mt][3], uAl + aoff);
            }
            #pragma unroll
            for (int np = 0; np < 4; np++) {
                uint32_t boff = (uint32_t)(((wn + np * 16 + b_row) * SA + s * 16 + b_kk) * 2);
                uint32_t bh0, bh1, bh2, bh3, bl0, bl1, bl2, bl3;
                ldm_x4(bh0, bh1, bh2, bh3, uBh + boff);
                ldm_x4(bl0, bl1, bl2, bl3, uBl + boff);
                #pragma unroll
                for (int mt = 0; mt < 2; mt++) {
                    mma_f16(acc[mt][np * 2],     ah[mt], bh0, bh1);
                    mma_f16(acc[mt][np * 2 + 1], ah[mt], bh2, bh3);
                    mma_f16(acc[mt][np * 2],     ah[mt], bl0, bl1);
                    mma_f16(acc[mt][np * 2 + 1], ah[mt], bl2, bl3);
                    mma_f16(acc[mt][np * 2],     al[mt], bh0, bh1);
                    mma_f16(acc[mt][np * 2 + 1], al[mt], bh2, bh3);
                }
            }
        }
        __syncthreads();
    }

    // fused epilogue
    #pragma unroll
    for (int mt = 0; mt < 2; mt++) {
        #pragma unroll
        for (int h = 0; h < 2; h++) {
            float s = 0.f;
            #pragma unroll
            for (int nt = 0; nt < 8; nt++) {
                int col = wn + nt * 8 + tig * 2;
                float v0 = acc[mt][nt][h * 2 + 0] + sb1[col];
                float v1 = acc[mt][nt][h * 2 + 1] + sb1[col + 1];
                s += fmaxf(v0, 0.f) * sw2[col] + fmaxf(v1, 0.f) * sw2[col + 1];
            }
            s += __shfl_xor_sync(0xFFFFFFFFu, s, 1);
            s += __shfl_xor_sync(0xFFFFFFFFu, s, 2);
            if (tig == 0) sred[warp_n][wm + mt * 16 + h * 8 + gid] = s;
        }
    }
    __syncthreads();
    if (tid < 128) {
        int row = m0 + tid;
        if (row < N)
            scores[row] = sred[0][tid] + sred[1][tid] + b2[0] + g_width[widx[row]];
    }
}

// ======================= selection: 8+8 bit radix locate =======================
__global__ void k_h8a(const float* __restrict__ scores, int N) {
    __shared__ int h[8][256];
    int t = threadIdx.x, w = t >> 5;
    for (int b = t; b < 2048; b += blockDim.x) ((int*)h)[b] = 0;
    __syncthreads();
    int i = blockIdx.x * blockDim.x + t;
    int stride = blockDim.x * gridDim.x;
    for (; i < N; i += stride) atomicAdd(&h[w][f2u(scores[i]) >> 24], 1);
    __syncthreads();
    for (int b = t; b < 256; b += blockDim.x) {
        int s = 0;
        #pragma unroll
        for (int ww = 0; ww < 8; ww++) s += h[ww][b];
        if (s) atomicAdd(&g_h8a[b], s);
    }
}

__global__ void k_f8a(int K) {
    if (threadIdx.x != 0) return;
    int cum = 0, b = 255;
    for (; b > 0; b--) { cum += g_h8a[b]; if (cum >= K) break; }
    if (cum < K) { cum += g_h8a[0]; b = 0; }
    g_bhi = b;
    g_needA = K - (cum - g_h8a[b]);
}

__global__ void k_h8b(const float* __restrict__ scores, int N) {
    __shared__ int h[8][256];
    int t = threadIdx.x, w = t >> 5;
    for (int b = t; b < 2048; b += blockDim.x) ((int*)h)[b] = 0;
    __syncthreads();
    int bhi = g_bhi;
    int i = blockIdx.x * blockDim.x + t;
    int stride = blockDim.x * gridDim.x;
    for (; i < N; i += stride) {
        unsigned u = f2u(scores[i]);
        if ((int)(u >> 24) == bhi) atomicAdd(&h[w][(u >> 16) & 0xFF], 1);
    }
    __syncthreads();
    for (int b = t; b < 256; b += blockDim.x) {
        int s = 0;
        #pragma unroll
        for (int ww = 0; ww < 8; ww++) s += h[ww][b];
        if (s) atomicAdd(&g_h8b[b], s);
    }
}

__global__ void k_f8b() {
    if (threadIdx.x != 0) return;
    int K = g_needA;
    int cum = 0, b = 255;
    for (; b > 0; b--) { cum += g_h8b[b]; if (cum >= K) break; }
    if (cum < K) { cum += g_h8b[0]; b = 0; }
    unsigned base = (((unsigned)g_bhi << 8) | (unsigned)b) << 16;
    unsigned top = base | 0xFFFFu;
    g_lou = (base >= MARGIN) ? base - MARGIN : 0u;
    g_hiu = (top <= 0xFFFFFFFFu - MARGIN) ? top + MARGIN : 0xFFFFFFFFu;
}

// ---- band list (uint-domain window around threshold bucket) ----
__global__ void k_bandlist(const float* __restrict__ scores, int N) {
    unsigned lo = g_lou, hi = g_hiu;
    int i = blockIdx.x * blockDim.x + threadIdx.x;
    if (i < N) {
        unsigned u = f2u(scores[i]);
        if (u >= lo && u <= hi) {
            int p = atomicAdd(&g_nband, 1);
            if (p < 65536) g_band[p] = i;
        }
    }
}

// ---- exact fp32 recompute of band rows ----
__global__ void k_exact(const float* __restrict__ x,
                        const float* __restrict__ W1, const float* __restrict__ b1,
                        const float* __restrict__ W2, const float* __restrict__ b2,
                        const int* __restrict__ widx, float* __restrict__ scores) {
    __shared__ float xs[1024];
    __shared__ float red[128];
    int nb = min(g_nband, 65536);
    int j = threadIdx.x;
    for (int it = blockIdx.x; it < nb; it += gridDim.x) {
        int i = g_band[it];
        for (int t = j; t < 1024; t += 128) xs[t] = x[(size_t)i * DSPAN + t];
        __syncthreads();
        float acc = b1[j];
        #pragma unroll 8
        for (int kk = 0; kk < 1024; kk++) acc += xs[kk] * W1[kk * HID + j];
        red[j] = fmaxf(acc, 0.f) * W2[j];
        __syncthreads();
        for (int s = 64; s > 0; s >>= 1) {
            if (j < s) red[j] += red[j + s];
            __syncthreads();
        }
        if (j == 0) scores[i] = red[0] + b2[0] + g_width[widx[i]];
        __syncthreads();
    }
}

// ---- count strictly above the band window (on repaired scores) ----
__global__ void k_cabove(const float* __restrict__ scores, int N) {
    unsigned hi = g_hiu;
    int t = threadIdx.x;
    int i = blockIdx.x * blockDim.x + t;
    int stride = blockDim.x * gridDim.x;
    int c = 0;
    for (; i < N; i += stride) c += (f2u(scores[i]) > hi) ? 1 : 0;
    for (int off = 16; off > 0; off >>= 1) c += __shfl_down_sync(0xFFFFFFFFu, c, off);
    __shared__ int red[32];
    if ((t & 31) == 0) red[t >> 5] = c;
    __syncthreads();
    if (t < 32) {
        int v = (t < (int)(blockDim.x >> 5)) ? red[t] : 0;
        for (int off = 16; off > 0; off >>= 1) v += __shfl_down_sync(0xFFFFFFFFu, v, off);
        if (t == 0 && v) atomicAdd(&g_cabove, v);
    }
}

// ---- rank-select the threshold among band members (single block) ----
__global__ void k_bandrank(const float* __restrict__ scores, int K) {
    __shared__ unsigned long long keys[4096];
    int m = min(g_nband, 4096);
    int need = K - g_cabove;
    unsigned hiu = g_hiu;
    for (int i = threadIdx.x; i < m; i += blockDim.x) {
        int idx = g_band[i];
        unsigned u = f2u(scores[idx]);
        keys[i] = (u > hiu) ? 0ULL
                : (((unsigned long long)u << 32) | (unsigned)(~(unsigned)idx));
    }
    __syncthreads();
    for (int i = threadIdx.x; i < m; i += blockDim.x) {
        unsigned long long ki = keys[i];
        if (ki == 0ULL) continue;
        int r = 0;
        for (int j = 0; j < m; j++) r += (keys[j] > ki) ? 1 : 0;
        if (r == need - 1) {
            g_thru = (unsigned)(ki >> 32);
            g_cut = (int)(~(unsigned)ki);
        }
    }
}

// ======================= ordered compaction =======================
__global__ void k_count(const float* __restrict__ scores, int N) {
    int t = threadIdx.x;
    unsigned thr = g_thru;
    int cut = g_cut;
    int base = blockIdx.x * 4096 + t * 4;
    int c = 0;
    #pragma unroll
    for (int e = 0; e < 4; e++) {
        int i = base + e;
        if (i < N && sel_pred(f2u(scores[i]), i, thr, cut)) c++;
    }
    for (int off = 16; off > 0; off >>= 1) c += __shfl_down_sync(0xFFFFFFFFu, c, off);
    __shared__ int red[32];
    if ((t & 31) == 0) red[t >> 5] = c;
    __syncthreads();
    if (t < 32) {
        int v = red[t];
        for (int off = 16; off > 0; off >>= 1) v += __shfl_down_sync(0xFFFFFFFFu, v, off);
        if (t == 0) g_bcnt[blockIdx.x] = v;
    }
}

__global__ void k_scanb(int nb) {
    __shared__ int s[256];
    int t = threadIdx.x;
    int v = (t < nb) ? g_bcnt[t] : 0;
    s[t] = v;
    __syncthreads();
    for (int off = 1; off < 256; off <<= 1) {
        int add = (t >= off) ? s[t - off] : 0;
        __syncthreads();
        s[t] += add;
        __syncthreads();
    }
    g_boff[t] = s[t] - v;
}

__global__ void k_scatter(const float* __restrict__ scores,
                          const int* __restrict__ beg, const int* __restrict__ end, int N,
                          float* __restrict__ o_ti, float* __restrict__ o_sc,
                          float* __restrict__ o_bg, float* __restrict__ o_en) {
    __shared__ int s[1024];
    int t = threadIdx.x;
    unsigned thr = g_thru;
    int cut = g_cut;
    int base = blockIdx.x * 4096 + t * 4;
    bool f[4];
    int c = 0;
    #pragma unroll
    for (int e = 0; e < 4; e++) {
        int i = base + e;
        f[e] = (i < N) && sel_pred(f2u(scores[i]), i, thr, cut);
        c += f[e] ? 1 : 0;
    }
    s[t] = c;
    __syncthreads();
    for (int off = 1; off < 1024; off <<= 1) {
        int add = (t >= off) ? s[t - off] : 0;
        __syncthreads();
        s[t] += add;
        __syncthreads();
    }
    int pos = g_boff[blockIdx.x] + s[t] - c;
    #pragma unroll
    for (int e = 0; e < 4; e++) {
        if (f[e]) {
            int i = base + e;
            g_topi[pos] = i;
            o_ti[pos] = (float)i;
            o_sc[pos] = scores[i];
            o_bg[pos] = (float)beg[i];
            o_en[pos] = (float)end[i];
            pos++;
        }
    }
}

__global__ void k_gather(const float* __restrict__ x, float* __restrict__ out) {
    int r = blockIdx.x;
    int src = g_topi[r];
    const float4* s = reinterpret_cast<const float4*>(x + (size_t)src * DSPAN);
    float4* d = reinterpret_cast<float4*>(out + (size_t)r * DSPAN);
    d[threadIdx.x] = s[threadIdx.x];
}

// ======================= launch =======================
extern "C" void kernel_launch(void* const* d_in, const int* in_sizes, int n_in,
                              void* d_out, int out_size) {
    const float* x    = (const float*)d_in[0];
    const int*   cbeg = (const int*)d_in[1];
    const int*   cend = (const int*)d_in[2];
    const int*   cwid = (const int*)d_in[3];
    const float* wemb = (const float*)d_in[4];
    const float* W1   = (const float*)d_in[5];
    const float* b1   = (const float*)d_in[6];
    const float* W2   = (const float*)d_in[7];
    const float* b2   = (const float*)d_in[8];
    const float* Ww1  = (const float*)d_in[9];
    const float* bw1  = (const float*)d_in[10];
    const float* Ww2  = (const float*)d_in[11];
    const float* bw2  = (const float*)d_in[12];

    int N = in_sizes[1];                 // 262144
    int D = in_sizes[0] / N;             // 1024
    int k = (out_size - N) / (D + 4);    // 3276

    float* out     = (float*)d_out;
    float* o_prune = out;                        // [N]
    float* o_vecs  = out + N;                    // [k, D]
    float* o_sc    = o_vecs + (size_t)k * D;     // [k]
    float* o_bg    = o_sc + k;                   // [k]
    float* o_en    = o_bg + k;                   // [k]
    float* o_ti    = o_en + k;                   // [k]

    k_setup<<<1, 256>>>();
    k_width<<<1, 128>>>(wemb, Ww1, bw1, Ww2, bw2);
    k_splitw<<<(DSPAN * HID + 255) / 256, 256>>>(W1);

    k_gemm_mma<<<N / 128, 256>>>(x, b1, W2, b2, cwid, o_prune, N);

    int nthr = (N + 255) / 256;
    k_h8a<<<256, 256>>>(o_prune, N);
    k_f8a<<<1, 32>>>(k);
    k_h8b<<<256, 256>>>(o_prune, N);
    k_f8b<<<1, 32>>>();
    k_bandlist<<<nthr, 256>>>(o_prune, N);
    k_exact<<<512, 128>>>(x, W1, b1, W2, b2, cwid, o_prune);
    k_cabove<<<256, 256>>>(o_prune, N);
    k_bandrank<<<1, 1024>>>(o_prune, k);

    int nb = (N + 4095) / 4096;          // 64
    k_count<<<nb, 1024>>>(o_prune, N);
    k_scanb<<<1, 256>>>(nb);
    k_scatter<<<nb, 1024>>>(o_prune, cbeg, cend, N, o_ti, o_sc, o_bg, o_en);

    k_gather<<<k, 256>>>(x, o_vecs);
}

// round 6
// speedup vs baseline: 5.0809x; 1.8622x over previous
#include <cuda_runtime.h>
#include <cuda_fp16.h>
#include <cstdint>

#define DSPAN 1024
#define HID   128
#define FEAT  20
#define NWID  30
#define MARGIN 8192u

// ======================= device scratch =======================
__device__ int      g_h8a[256];
__device__ int      g_h8b[256];
__device__ int      g_bhi, g_needA;
__device__ unsigned g_lou, g_hiu;
__device__ int      g_nband, g_cabove;
__device__ unsigned g_thru;
__device__ int      g_cut;
__device__ int      g_bcnt[256];
__device__ int      g_boff[256];
__device__ int      g_topi[4096];
__device__ float    g_width[32];
__device__ int      g_band[65536];
// W1 transposed [H][D] fp16
__device__ __align__(16) __half g_w1t[HID * DSPAN];

__device__ __forceinline__ unsigned f2u(float f) {
    unsigned b = __float_as_uint(f);
    return b ^ ((unsigned)((int)b >> 31) | 0x80000000u);
}
__device__ __forceinline__ bool sel_pred(unsigned u, int i, unsigned thr, int cut) {
    return (u > thr) || (u == thr && i <= cut);
}
__device__ __forceinline__ uint32_t smem_u32(const void* p) {
    uint32_t a;
    asm("{ .reg .u64 t; cvta.to.shared.u64 t, %1; cvt.u32.u64 %0, t; }" : "=r"(a) : "l"(p));
    return a;
}
__device__ __forceinline__ void ldm_x4(uint32_t& r0, uint32_t& r1, uint32_t& r2, uint32_t& r3, uint32_t a) {
    asm volatile("ldmatrix.sync.aligned.m8n8.x4.shared.b16 {%0,%1,%2,%3}, [%4];"
                 : "=r"(r0), "=r"(r1), "=r"(r2), "=r"(r3) : "r"(a));
}
__device__ __forceinline__ void mma_f16(float* d, const uint32_t* a, uint32_t b0, uint32_t b1) {
    asm volatile(
        "mma.sync.aligned.m16n8k16.row.col.f32.f16.f16.f32 "
        "{%0,%1,%2,%3}, {%4,%5,%6,%7}, {%8,%9}, {%0,%1,%2,%3};"
        : "+f"(d[0]), "+f"(d[1]), "+f"(d[2]), "+f"(d[3])
        : "r"(a[0]), "r"(a[1]), "r"(a[2]), "r"(a[3]), "r"(b0), "r"(b1));
}
__device__ __forceinline__ unsigned pack_h2(__half a, __half b) {
    return (unsigned)__half_as_ushort(a) | ((unsigned)__half_as_ushort(b) << 16);
}
__device__ __forceinline__ void cp_async16(uint32_t dst, const void* src) {
    asm volatile("cp.async.ca.shared.global [%0], [%1], 16;" :: "r"(dst), "l"(src));
}

// ======================= setup =======================
__global__ void k_setup() {
    int i = threadIdx.x;
    if (i < 256) { g_h8a[i] = 0; g_h8b[i] = 0; }
    if (i == 0) { g_nband = 0; g_cabove = 0; }
}

// ======================= width prior =======================
__global__ void k_width(const float* __restrict__ emb,
                        const float* __restrict__ Ww1, const float* __restrict__ bw1,
                        const float* __restrict__ Ww2, const float* __restrict__ bw2) {
    __shared__ float red[128];
    int j = threadIdx.x;
    for (int w = 0; w < NWID; w++) {
        float acc = bw1[j];
        #pragma unroll
        for (int kk = 0; kk < FEAT; kk++)
            acc += emb[w * FEAT + kk] * Ww1[kk * HID + j];
        red[j] = fmaxf(acc, 0.f) * Ww2[j];
        __syncthreads();
        for (int s = 64; s > 0; s >>= 1) {
            if (j < s) red[j] += red[j + s];
            __syncthreads();
        }
        if (j == 0) g_width[w] = red[0] + bw2[0];
        __syncthreads();
    }
}

// ======================= W1 transpose -> fp16 =======================
__global__ void k_cvtw(const float* __restrict__ W1) {
    int i = blockIdx.x * blockDim.x + threadIdx.x;
    if (i < DSPAN * HID) {
        int kk = i >> 7, n = i & 127;
        g_w1t[n * DSPAN + kk] = __float2half_rn(W1[i]);
    }
}

// ======================= fp16 warp-MMA GEMM, double-buffered =======================
// CTA: 128 rows x 128 cols (full H). 8 warps = 4(M) x 2(N), warp tile 32x64.
// K chunked by 32. smem rows padded to 40 halfs (80B).
#define SA 40
#define TILE_H (128 * SA)          // halfs per tile
__global__ __launch_bounds__(256, 2)
void k_gemm_mma(const float* __restrict__ x,
                const float* __restrict__ b1, const float* __restrict__ W2,
                const float* __restrict__ b2, const int* __restrict__ widx,
                float* __restrict__ scores, int N) {
    __shared__ __align__(16) __half sA[2][TILE_H];
    __shared__ __align__(16) __half sB[2][TILE_H];
    __shared__ float sb1[128], sw2[128];
    __shared__ float sred[2][128];

    int tid = threadIdx.x;
    int wid = tid >> 5, lid = tid & 31;
    int warp_m = wid & 3, warp_n = wid >> 2;      // 4 x 2
    int wm = warp_m * 32, wn = warp_n * 64;
    int gid = lid >> 2, tig = lid & 3;
    int m0 = blockIdx.x * 128;

    if (tid < 128) { sb1[tid] = b1[tid]; sw2[tid] = W2[tid]; }

    float acc[2][8][4];
    #pragma unroll
    for (int mt = 0; mt < 2; mt++)
        #pragma unroll
        for (int nt = 0; nt < 8; nt++)
            #pragma unroll
            for (int q = 0; q < 4; q++) acc[mt][nt][q] = 0.f;

    const float* xblk = x + (size_t)m0 * DSPAN;
    uint32_t uA0 = smem_u32(sA[0]), uA1 = smem_u32(sA[1]);
    uint32_t uB0 = smem_u32(sB[0]), uB1 = smem_u32(sB[1]);

    // per-thread load geometry
    int a_ld_row = tid >> 3, a_ld_c4 = tid & 7;          // +64 rows for p=1..3 via g
    int b_ld_row = tid >> 2, b_ld_seg = tid & 3;         // +64 rows for p=1

    // ldmatrix lane addressing
    int a_row = (lid & 15);
    int a_kk  = (lid >> 4) << 3;
    int b_row = (lid & 7) + ((lid & 16) ? 8 : 0);
    int b_kk  = (lid & 8);

    float4 aR[4];

    auto ldg_a = [&](int ch) {
        int kt = ch * 32;
        #pragma unroll
        for (int p = 0; p < 4; p++) {
            int row = a_ld_row + p * 32;
            aR[p] = *reinterpret_cast<const float4*>(xblk + (size_t)row * DSPAN + kt + a_ld_c4 * 4);
        }
    };
    auto cpasync_b = [&](int ch, uint32_t uB) {
        int kt = ch * 32;
        #pragma unroll
        for (int p = 0; p < 2; p++) {
            int row = b_ld_row + p * 64;
            const void* src = &g_w1t[(size_t)row * DSPAN + kt + b_ld_seg * 8];
            cp_async16(uB + (uint32_t)(row * SA + b_ld_seg * 8) * 2, src);
        }
        asm volatile("cp.async.commit_group;");
    };
    auto sts_a = [&](__half* dstA) {
        #pragma unroll
        for (int p = 0; p < 4; p++) {
            int row = a_ld_row + p * 32;
            float4 v = aR[p];
            unsigned u0 = pack_h2(__float2half_rn(v.x), __float2half_rn(v.y));
            unsigned u1 = pack_h2(__float2half_rn(v.z), __float2half_rn(v.w));
            *reinterpret_cast<uint2*>(&dstA[row * SA + a_ld_c4 * 4]) = make_uint2(u0, u1);
        }
    };

    // prologue: chunk 0 into buffer 0
    ldg_a(0);
    cpasync_b(0, uB0);
    sts_a(sA[0]);
    asm volatile("cp.async.wait_group 0;");
    __syncthreads();

    int buf = 0;
    for (int ch = 0; ch < 32; ch++) {
        uint32_t uA = buf ? uA1 : uA0;
        uint32_t uB = buf ? uB1 : uB0;
        if (ch < 31) {
            ldg_a(ch + 1);                       // LDGs in flight during MMAs
            cpasync_b(ch + 1, buf ? uB0 : uB1);  // async into next buffer
        }

        #pragma unroll
        for (int s = 0; s < 2; s++) {
            uint32_t ah[2][4];
            #pragma unroll
            for (int mt = 0; mt < 2; mt++) {
                uint32_t aoff = (uint32_t)(((wm + mt * 16 + a_row) * SA + s * 16 + a_kk) * 2);
                ldm_x4(ah[mt][0], ah[mt][1], ah[mt][2], ah[mt][3], uA + aoff);
            }
            #pragma unroll
            for (int np = 0; np < 4; np++) {
                uint32_t boff = (uint32_t)(((wn + np * 16 + b_row) * SA + s * 16 + b_kk) * 2);
                uint32_t b0, b1v, b2v, b3;
                ldm_x4(b0, b1v, b2v, b3, uB + boff);
                #pragma unroll
                for (int mt = 0; mt < 2; mt++) {
                    mma_f16(acc[mt][np * 2],     ah[mt], b0, b1v);
                    mma_f16(acc[mt][np * 2 + 1], ah[mt], b2v, b3);
                }
            }
        }

        if (ch < 31) {
            sts_a(buf ? sA[0] : sA[1]);
            asm volatile("cp.async.wait_group 0;");
        }
        __syncthreads();
        buf ^= 1;
    }

    // fused epilogue: relu + bias, dot W2, reduce
    #pragma unroll
    for (int mt = 0; mt < 2; mt++) {
        #pragma unroll
        for (int h = 0; h < 2; h++) {
            float s = 0.f;
            #pragma unroll
            for (int nt = 0; nt < 8; nt++) {
                int col = wn + nt * 8 + tig * 2;
                float v0 = acc[mt][nt][h * 2 + 0] + sb1[col];
                float v1 = acc[mt][nt][h * 2 + 1] + sb1[col + 1];
                s += fmaxf(v0, 0.f) * sw2[col] + fmaxf(v1, 0.f) * sw2[col + 1];
            }
            s += __shfl_xor_sync(0xFFFFFFFFu, s, 1);
            s += __shfl_xor_sync(0xFFFFFFFFu, s, 2);
            if (tig == 0) sred[warp_n][wm + mt * 16 + h * 8 + gid] = s;
        }
    }
    __syncthreads();
    if (tid < 128) {
        int row = m0 + tid;
        if (row < N)
            scores[row] = sred[0][tid] + sred[1][tid] + b2[0] + g_width[widx[row]];
    }
}

// ======================= selection: 8+8 bit radix locate =======================
__global__ void k_h8a(const float* __restrict__ scores, int N) {
    __shared__ int h[8][256];
    int t = threadIdx.x, w = t >> 5;
    for (int b = t; b < 2048; b += blockDim.x) ((int*)h)[b] = 0;
    __syncthreads();
    int i = blockIdx.x * blockDim.x + t;
    int stride = blockDim.x * gridDim.x;
    for (; i < N; i += stride) atomicAdd(&h[w][f2u(scores[i]) >> 24], 1);
    __syncthreads();
    for (int b = t; b < 256; b += blockDim.x) {
        int s = 0;
        #pragma unroll
        for (int ww = 0; ww < 8; ww++) s += h[ww][b];
        if (s) atomicAdd(&g_h8a[b], s);
    }
}

__global__ void k_f8a(int K) {
    if (threadIdx.x != 0) return;
    int cum = 0, b = 255;
    for (; b > 0; b--) { cum += g_h8a[b]; if (cum >= K) break; }
    if (cum < K) { cum += g_h8a[0]; b = 0; }
    g_bhi = b;
    g_needA = K - (cum - g_h8a[b]);
}

__global__ void k_h8b(const float* __restrict__ scores, int N) {
    __shared__ int h[8][256];
    int t = threadIdx.x, w = t >> 5;
    for (int b = t; b < 2048; b += blockDim.x) ((int*)h)[b] = 0;
    __syncthreads();
    int bhi = g_bhi;
    int i = blockIdx.x * blockDim.x + t;
    int stride = blockDim.x * gridDim.x;
    for (; i < N; i += stride) {
        unsigned u = f2u(scores[i]);
        if ((int)(u >> 24) == bhi) atomicAdd(&h[w][(u >> 16) & 0xFF], 1);
    }
    __syncthreads();
    for (int b = t; b < 256; b += blockDim.x) {
        int s = 0;
        #pragma unroll
        for (int ww = 0; ww < 8; ww++) s += h[ww][b];
        if (s) atomicAdd(&g_h8b[b], s);
    }
}

__global__ void k_f8b() {
    if (threadIdx.x != 0) return;
    int K = g_needA;
    int cum = 0, b = 255;
    for (; b > 0; b--) { cum += g_h8b[b]; if (cum >= K) break; }
    if (cum < K) { cum += g_h8b[0]; b = 0; }
    unsigned base = (((unsigned)g_bhi << 8) | (unsigned)b) << 16;
    unsigned top = base | 0xFFFFu;
    g_lou = (base >= MARGIN) ? base - MARGIN : 0u;
    g_hiu = (top <= 0xFFFFFFFFu - MARGIN) ? top + MARGIN : 0xFFFFFFFFu;
}

// ---- band list (uint-domain window around threshold bucket) ----
__global__ void k_bandlist(const float* __restrict__ scores, int N) {
    unsigned lo = g_lou, hi = g_hiu;
    int i = blockIdx.x * blockDim.x + threadIdx.x;
    if (i < N) {
        unsigned u = f2u(scores[i]);
        if (u >= lo && u <= hi) {
            int p = atomicAdd(&g_nband, 1);
            if (p < 65536) g_band[p] = i;
        }
    }
}

// ---- exact fp32 recompute of band rows ----
__global__ void k_exact(const float* __restrict__ x,
                        const float* __restrict__ W1, const float* __restrict__ b1,
                        const float* __restrict__ W2, const float* __restrict__ b2,
                        const int* __restrict__ widx, float* __restrict__ scores) {
    __shared__ float xs[1024];
    __shared__ float red[128];
    int nb = min(g_nband, 65536);
    int j = threadIdx.x;
    for (int it = blockIdx.x; it < nb; it += gridDim.x) {
        int i = g_band[it];
        for (int t = j; t < 1024; t += 128) xs[t] = x[(size_t)i * DSPAN + t];
        __syncthreads();
        float acc = b1[j];
        #pragma unroll 8
        for (int kk = 0; kk < 1024; kk++) acc += xs[kk] * W1[kk * HID + j];
        red[j] = fmaxf(acc, 0.f) * W2[j];
        __syncthreads();
        for (int s = 64; s > 0; s >>= 1) {
            if (j < s) red[j] += red[j + s];
            __syncthreads();
        }
        if (j == 0) scores[i] = red[0] + b2[0] + g_width[widx[i]];
        __syncthreads();
    }
}

// ---- count strictly above the band window (on repaired scores) ----
__global__ void k_cabove(const float* __restrict__ scores, int N) {
    unsigned hi = g_hiu;
    int t = threadIdx.x;
    int i = blockIdx.x * blockDim.x + t;
    int stride = blockDim.x * gridDim.x;
    int c = 0;
    for (; i < N; i += stride) c += (f2u(scores[i]) > hi) ? 1 : 0;
    for (int off = 16; off > 0; off >>= 1) c += __shfl_down_sync(0xFFFFFFFFu, c, off);
    __shared__ int red[32];
    if ((t & 31) == 0) red[t >> 5] = c;
    __syncthreads();
    if (t < 32) {
        int v = (t < (int)(blockDim.x >> 5)) ? red[t] : 0;
        for (int off = 16; off > 0; off >>= 1) v += __shfl_down_sync(0xFFFFFFFFu, v, off);
        if (t == 0 && v) atomicAdd(&g_cabove, v);
    }
}

// ---- rank-select the threshold among band members (single block) ----
__global__ void k_bandrank(const float* __restrict__ scores, int K) {
    __shared__ unsigned long long keys[4096];
    int m = min(g_nband, 4096);
    int need = K - g_cabove;
    unsigned hiu = g_hiu;
    for (int i = threadIdx.x; i < m; i += blockDim.x) {
        int idx = g_band[i];
        unsigned u = f2u(scores[idx]);
        keys[i] = (u > hiu) ? 0ULL
                : (((unsigned long long)u << 32) | (unsigned)(~(unsigned)idx));
    }
    __syncthreads();
    for (int i = threadIdx.x; i < m; i += blockDim.x) {
        unsigned long long ki = keys[i];
        if (ki == 0ULL) continue;
        int r = 0;
        for (int j = 0; j < m; j++) r += (keys[j] > ki) ? 1 : 0;
        if (r == need - 1) {
            g_thru = (unsigned)(ki >> 32);
            g_cut = (int)(~(unsigned)ki);
        }
    }
}

// ======================= ordered compaction =======================
__global__ void k_count(const float* __restrict__ scores, int N) {
    int t = threadIdx.x;
    unsigned thr = g_thru;
    int cut = g_cut;
    int base = blockIdx.x * 4096 + t * 4;
    int c = 0;
    #pragma unroll
    for (int e = 0; e < 4; e++) {
        int i = base + e;
        if (i < N && sel_pred(f2u(scores[i]), i, thr, cut)) c++;
    }
    for (int off = 16; off > 0; off >>= 1) c += __shfl_down_sync(0xFFFFFFFFu, c, off);
    __shared__ int red[32];
    if ((t & 31) == 0) red[t >> 5] = c;
    __syncthreads();
    if (t < 32) {
        int v = red[t];
        for (int off = 16; off > 0; off >>= 1) v += __shfl_down_sync(0xFFFFFFFFu, v, off);
        if (t == 0) g_bcnt[blockIdx.x] = v;
    }
}

__global__ void k_scanb(int nb) {
    __shared__ int s[256];
    int t = threadIdx.x;
    int v = (t < nb) ? g_bcnt[t] : 0;
    s[t] = v;
    __syncthreads();
    for (int off = 1; off < 256; off <<= 1) {
        int add = (t >= off) ? s[t - off] : 0;
        __syncthreads();
        s[t] += add;
        __syncthreads();
    }
    g_boff[t] = s[t] - v;
}

__global__ void k_scatter(const float* __restrict__ scores,
                          const int* __restrict__ beg, const int* __restrict__ end, int N,
                          float* __restrict__ o_ti, float* __restrict__ o_sc,
                          float* __restrict__ o_bg, float* __restrict__ o_en) {
    __shared__ int s[1024];
    int t = threadIdx.x;
    unsigned thr = g_thru;
    int cut = g_cut;
    int base = blockIdx.x * 4096 + t * 4;
    bool f[4];
    int c = 0;
    #pragma unroll
    for (int e = 0; e < 4; e++) {
        int i = base + e;
        f[e] = (i < N) && sel_pred(f2u(scores[i]), i, thr, cut);
        c += f[e] ? 1 : 0;
    }
    s[t] = c;
    __syncthreads();
    for (int off = 1; off < 1024; off <<= 1) {
        int add = (t >= off) ? s[t - off] : 0;
        __syncthreads();
        s[t] += add;
        __syncthreads();
    }
    int pos = g_boff[blockIdx.x] + s[t] - c;
    #pragma unroll
    for (int e = 0; e < 4; e++) {
        if (f[e]) {
            int i = base + e;
            g_topi[pos] = i;
            o_ti[pos] = (float)i;
            o_sc[pos] = scores[i];
            o_bg[pos] = (float)beg[i];
            o_en[pos] = (float)end[i];
            pos++;
        }
    }
}

__global__ void k_gather(const float* __restrict__ x, float* __restrict__ out) {
    int r = blockIdx.x;
    int src = g_topi[r];
    const float4* s = reinterpret_cast<const float4*>(x + (size_t)src * DSPAN);
    float4* d = reinterpret_cast<float4*>(out + (size_t)r * DSPAN);
    d[threadIdx.x] = s[threadIdx.x];
}

// ======================= launch =======================
extern "C" void kernel_launch(void* const* d_in, const int* in_sizes, int n_in,
                              void* d_out, int out_size) {
    const float* x    = (const float*)d_in[0];
    const int*   cbeg = (const int*)d_in[1];
    const int*   cend = (const int*)d_in[2];
    const int*   cwid = (const int*)d_in[3];
    const float* wemb = (const float*)d_in[4];
    const float* W1   = (const float*)d_in[5];
    const float* b1   = (const float*)d_in[6];
    const float* W2   = (const float*)d_in[7];
    const float* b2   = (const float*)d_in[8];
    const float* Ww1  = (const float*)d_in[9];
    const float* bw1  = (const float*)d_in[10];
    const float* Ww2  = (const float*)d_in[11];
    const float* bw2  = (const float*)d_in[12];

    int N = in_sizes[1];                 // 262144
    int D = in_sizes[0] / N;             // 1024
    int k = (out_size - N) / (D + 4);    // 3276

    float* out     = (float*)d_out;
    float* o_prune = out;                        // [N]
    float* o_vecs  = out + N;                    // [k, D]
    float* o_sc    = o_vecs + (size_t)k * D;     // [k]
    float* o_bg    = o_sc + k;                   // [k]
    float* o_en    = o_bg + k;                   // [k]
    float* o_ti    = o_en + k;                   // [k]

    k_setup<<<1, 256>>>();
    k_width<<<1, 128>>>(wemb, Ww1, bw1, Ww2, bw2);
    k_cvtw<<<(DSPAN * HID + 255) / 256, 256>>>(W1);

    k_gemm_mma<<<N / 128, 256>>>(x, b1, W2, b2, cwid, o_prune, N);

    int nthr = (N + 255) / 256;
    k_h8a<<<256, 256>>>(o_prune, N);
    k_f8a<<<1, 32>>>(k);
    k_h8b<<<256, 256>>>(o_prune, N);
    k_f8b<<<1, 32>>>();
    k_bandlist<<<nthr, 256>>>(o_prune, N);
    k_exact<<<512, 128>>>(x, W1, b1, W2, b2, cwid, o_prune);
    k_cabove<<<256, 256>>>(o_prune, N);
    k_bandrank<<<1, 1024>>>(o_prune, k);

    int nb = (N + 4095) / 4096;          // 64
    k_count<<<nb, 1024>>>(o_prune, N);
    k_scanb<<<1, 256>>>(nb);
    k_scatter<<<nb, 1024>>>(o_prune, cbeg, cend, N, o_ti, o_sc, o_bg, o_en);

    k_gather<<<k, 256>>>(x, o_vecs);
}